// round 11
// baseline (speedup 1.0000x reference)
#include <cuda_runtime.h>
#include <cuda_bf16.h>
#include <math.h>

// Problem constants
#define ROWS_TOTAL 32768
#define K_DIM 1024
#define ANCHORS 8
#define PRED_ELEMS (ROWS_TOTAL * ANCHORS)   // 262144

// One 512-thread CTA = 16 autonomous warps in 8 pairs. Pair p owns 8 rows;
// within a pair, warp h=wid&1 computes anchors h*4..h*4+3 (8 outputs).
#define THREADS 512
#define WARPS_PER_BLOCK 16
#define ROWS_PER_WARP 8
#define ROWS_PER_BLOCK 64
#define NBLOCKS (ROWS_TOTAL / ROWS_PER_BLOCK)   // 512
#define NCHUNKS 32                              // K chunks of 32
#define NBUF 8                                  // per-warp X ring depth (pow2)
#define LOOKAHEAD 6

// W in shared, padded stride 20 floats. 8-lane LDS.128 phase banks
// (20L + const) mod 32 cover all 32 banks once -> conflict-free.
#define W_STRIDE 20
#define W_FLOATS (K_DIM * W_STRIDE)             // 80KB
// Per-warp X ring: NBUF chunks x (8 rows x 32 k) = 8*256 floats = 8KB
#define XCHUNK_FLOATS 256
#define XW_FLOATS (NBUF * XCHUNK_FLOATS)
#define SMEM_BYTES ((W_FLOATS + WARPS_PER_BLOCK * XW_FLOATS) * 4)  // 208KB

__device__ float g_part_nll[NBLOCKS];
__device__ int   g_part_cnt[NBLOCKS];
__device__ unsigned int g_done;   // zero-init; finalizer resets -> replay-safe

__device__ __forceinline__ void fma2(unsigned long long& d,
                                     unsigned long long a,
                                     unsigned long long b) {
    asm("fma.rn.f32x2 %0, %1, %2, %0;" : "+l"(d) : "l"(a), "l"(b));
}
__device__ __forceinline__ unsigned long long add2r(unsigned long long a,
                                                    unsigned long long b) {
    asm("add.rn.f32x2 %0, %0, %1;" : "+l"(a) : "l"(b));
    return a;
}
__device__ __forceinline__ unsigned long long pack_dup(float x) {
    unsigned long long r;
    asm("mov.b64 %0, {%1, %1};" : "=l"(r) : "r"(__float_as_uint(x)));
    return r;
}
__device__ __forceinline__ void unpack2(unsigned long long v, float& lo, float& hi) {
    unsigned int l, h;
    asm("mov.b64 {%0, %1}, %2;" : "=r"(l), "=r"(h) : "l"(v));
    lo = __uint_as_float(l);
    hi = __uint_as_float(h);
}
__device__ __forceinline__ void cp_async16(unsigned int sdst, const void* gsrc) {
    asm volatile("cp.async.cg.shared.global [%0], [%1], 16;"
                 :: "r"(sdst), "l"(gsrc) : "memory");
}
__device__ __forceinline__ void cp_commit() {
    asm volatile("cp.async.commit_group;" ::: "memory");
}
template <int N>
__device__ __forceinline__ void cp_wait() {
    asm volatile("cp.async.wait_group %0;" :: "n"(N) : "memory");
}

// Per-chunk register stage: 8 W floats (4 f32x2) + 8 X floats
struct Chunk {
    ulonglong2 wa, wb;
    float xr[ROWS_PER_WARP];
};

__device__ __forceinline__ void load_chunk(Chunk& ch, const float* __restrict__ wbase,
                                           const float* __restrict__ xw,
                                           int c, int lane) {
    const float* wp = wbase + (c * 32 + lane) * W_STRIDE;
    ch.wa = *reinterpret_cast<const ulonglong2*>(wp);
    ch.wb = *reinterpret_cast<const ulonglong2*>(wp + 4);
    const float* xb = xw + (c & (NBUF - 1)) * XCHUNK_FLOATS + lane;
#pragma unroll
    for (int r = 0; r < ROWS_PER_WARP; ++r) ch.xr[r] = xb[r * 32];
}

__device__ __forceinline__ void compute_chunk(unsigned long long* __restrict__ acc,
                                              const Chunk& ch) {
#pragma unroll
    for (int r = 0; r < ROWS_PER_WARP; ++r) {
        const unsigned long long xx = pack_dup(ch.xr[r]);
        fma2(acc[r * 4 + 0], xx, ch.wa.x);
        fma2(acc[r * 4 + 1], xx, ch.wa.y);
        fma2(acc[r * 4 + 2], xx, ch.wb.x);
        fma2(acc[r * 4 + 3], xx, ch.wb.y);
    }
}

__global__ __launch_bounds__(THREADS, 1)
void rpn_main_kernel(const float*  __restrict__ Xf,     // [32768][1024]
                     const float*  __restrict__ Wg,     // [1024][16]
                     const float*  __restrict__ bias,   // [16]
                     const int*    __restrict__ labels, // [32768][8]
                     float* __restrict__ out)
{
    extern __shared__ __align__(16) float smem[];
    float* Wsh = smem;                        // [1024][20]
    float* Xsh = smem + W_FLOATS;             // [16 warps][NBUF][256]
    __shared__ float s_nll[WARPS_PER_BLOCK];
    __shared__ int   s_cnt[WARPS_PER_BLOCK];
    __shared__ int   s_last;

    const int tid  = threadIdx.x;
    const int wid  = tid >> 5;
    const int lane = tid & 31;
    const int pair = wid >> 1;            // 0..7
    const int h    = wid & 1;             // anchor half
    const int row0 = blockIdx.x * ROWS_PER_BLOCK;
    const int wrow0 = row0 + pair * ROWS_PER_WARP;

    float* xw = Xsh + wid * XW_FLOATS;
    const unsigned int xw_u32 = (unsigned int)__cvta_generic_to_shared(xw);
    const float* wbase = Wsh + h * 8;     // this warp's anchor half within W rows

    // Staging: 8 rows x 8 segs of 16B = 64 cp per chunk, 2 per lane.
    // Lane L: seg s=L&7 of rows r0=L>>3 and r0+4.
    const int st_r = lane >> 3;
    const int st_s = lane & 7;
    const char* gb0 = (const char*)(Xf + (size_t)(wrow0 + st_r) * K_DIM) + st_s * 16;
    const char* gb1 = gb0 + 4 * K_DIM * 4;                 // +4 rows
    const unsigned int sb0 = xw_u32 + st_r * 128 + st_s * 16;
    const unsigned int sb1 = sb0 + 4 * 128;

    // Prologue: start chunks 0..LOOKAHEAD-1 (1 commit group per chunk)
#pragma unroll
    for (int j = 0; j < LOOKAHEAD; ++j) {
        cp_async16(sb0 + j * 1024, gb0 + j * 128);
        cp_async16(sb1 + j * 1024, gb1 + j * 128);
        cp_commit();
    }

    // Stage W (vectorized STS.128 into padded layout) while X flows
    {
        const float4* Wg4 = reinterpret_cast<const float4*>(Wg);
        for (int i = tid; i < K_DIM * 4; i += THREADS) {
            const int k  = i >> 2;
            const int n0 = (i & 3) * 4;
            *reinterpret_cast<float4*>(Wsh + k * W_STRIDE + n0) = Wg4[i];
        }
    }
    __syncthreads();   // W visible to all warps

    // acc[r*4+p] packs (anchor h*4+p: class0, class1) for local row r (0..7)
    unsigned long long acc[32];
#pragma unroll
    for (int j = 0; j < 32; ++j) acc[j] = 0ULL;

    Chunk ch0, ch1;
    cp_wait<LOOKAHEAD - 2>();   // chunks 0 and 1 resident
    __syncwarp();
    load_chunk(ch0, wbase, xw, 0, lane);
    load_chunk(ch1, wbase, xw, 1, lane);

    // Main loop, unrolled by 2 (ping-pong, no struct copies).
    // Iter c computes chunks c, c+1 and reloads ch0<-c+2, ch1<-c+3.
    // Group accounting: after prefetching c+L and c+L+1, groups younger than
    // chunk c+2 number L-1 -> wait<L-1>; younger than c+3 -> wait<L-2>.
#pragma unroll 1
    for (int c = 0; c <= NCHUNKS - 2 - LOOKAHEAD; c += 2) {
        cp_async16(sb0 + ((c + LOOKAHEAD) & (NBUF - 1)) * 1024,
                   gb0 + (c + LOOKAHEAD) * 128);
        cp_async16(sb1 + ((c + LOOKAHEAD) & (NBUF - 1)) * 1024,
                   gb1 + (c + LOOKAHEAD) * 128);
        cp_commit();
        cp_async16(sb0 + ((c + LOOKAHEAD + 1) & (NBUF - 1)) * 1024,
                   gb0 + (c + LOOKAHEAD + 1) * 128);
        cp_async16(sb1 + ((c + LOOKAHEAD + 1) & (NBUF - 1)) * 1024,
                   gb1 + (c + LOOKAHEAD + 1) * 128);
        cp_commit();

        cp_wait<LOOKAHEAD - 1>();   // chunk c+2 resident
        __syncwarp();
        compute_chunk(acc, ch0);
        load_chunk(ch0, wbase, xw, c + 2, lane);

        cp_wait<LOOKAHEAD - 2>();   // chunk c+3 resident
        __syncwarp();
        compute_chunk(acc, ch1);
        load_chunk(ch1, wbase, xw, c + 3, lane);
    }
    // After loop (c stopped at 24): chunks 0..25 computed, ch0=26, ch1=27,
    // all 32 chunks issued. Drain and finish resident tail.
    cp_wait<0>();
    __syncwarp();
    compute_chunk(acc, ch0);
    compute_chunk(acc, ch1);
#pragma unroll
    for (int c = NCHUNKS - LOOKAHEAD + 2; c < NCHUNKS; ++c) {   // 28..31
        load_chunk(ch0, wbase, xw, c, lane);
        compute_chunk(acc, ch0);
    }

    // Multi-value butterfly: 32 packed values over 32 lanes -> 1 per lane.
    // Lane L ends owning value j=L: local row L>>2, anchor-sub L&3.
#pragma unroll
    for (int lvl = 0; lvl < 5; ++lvl) {
        const int m = 16 >> lvl;
        const bool up = (lane & m) != 0;
#pragma unroll
        for (int i = 0; i < 32; ++i) {
            if (i >= m) continue;
            const unsigned long long sent = up ? acc[i] : acc[m + i];
            const unsigned long long rcv = __shfl_xor_sync(0xffffffffu, sent, m);
            acc[i] = up ? add2r(acc[m + i], rcv) : add2r(acc[i], rcv);
        }
    }

    // Epilogue: one (row, anchor) per lane
    const int r_loc = lane >> 2;
    const int a = h * 4 + (lane & 3);
    const int row = wrow0 + r_loc;

    float l0, l1;
    unpack2(acc[0], l0, l1);
    l0 += __ldg(&bias[2 * a]);
    l1 += __ldg(&bias[2 * a + 1]);

    const int lab = __ldg(&labels[row * ANCHORS + a]);
    const bool valid = (lab != -1);
    const int pred = (l1 > l0) ? 1 : 0;   // argmax, tie -> 0

    const float mx = fmaxf(l0, l1);
    const float mn = fminf(l0, l1);
    const float lse = mx + log1pf(expf(mn - mx));
    const float picked = (lab > 0) ? l1 : l0;   // clamp(-1)->0 picks l0
    const float nll = valid ? (lse - picked) : 0.0f;

    const int idx = row * ANCHORS + a;
    out[1 + idx] = (float)pred;
    out[1 + PRED_ELEMS + idx] = (pred == 1 && valid) ? 1.0f : 0.0f;

    // Loss: warp -> block -> per-block partial
    float nll_w = nll;
    int cnt_w = valid ? 1 : 0;
#pragma unroll
    for (int s = 16; s > 0; s >>= 1) {
        nll_w += __shfl_xor_sync(0xffffffffu, nll_w, s);
        cnt_w += __shfl_xor_sync(0xffffffffu, cnt_w, s);
    }
    if (lane == 0) { s_nll[wid] = nll_w; s_cnt[wid] = cnt_w; }
    __syncthreads();

    if (tid == 0) {
        float bn = 0.f; int bc = 0;
#pragma unroll
        for (int i = 0; i < WARPS_PER_BLOCK; ++i) { bn += s_nll[i]; bc += s_cnt[i]; }
        g_part_nll[blockIdx.x] = bn;
        g_part_cnt[blockIdx.x] = bc;
        __threadfence();
        const unsigned int old = atomicAdd(&g_done, 1u);
        s_last = (old == NBLOCKS - 1) ? 1 : 0;
    }
    __syncthreads();

    // Last-arriving block performs the final loss reduction (no extra launch).
    if (s_last) {
        __shared__ double f_sum[WARPS_PER_BLOCK];
        __shared__ int    f_cnt[WARPS_PER_BLOCK];
        double sum = (double)g_part_nll[tid];   // NBLOCKS == THREADS
        int cnt = g_part_cnt[tid];
#pragma unroll
        for (int s = 16; s > 0; s >>= 1) {
            sum += __shfl_xor_sync(0xffffffffu, sum, s);
            cnt += __shfl_xor_sync(0xffffffffu, cnt, s);
        }
        if (lane == 0) { f_sum[wid] = sum; f_cnt[wid] = cnt; }
        __syncthreads();
        if (tid == 0) {
            double t = 0.0; int c = 0;
#pragma unroll
            for (int i = 0; i < WARPS_PER_BLOCK; ++i) { t += f_sum[i]; c += f_cnt[i]; }
            const double denom = c > 1 ? (double)c : 1.0;
            out[0] = (float)(t / denom);
            g_done = 0u;   // reset for next graph replay
        }
    }
}

extern "C" void kernel_launch(void* const* d_in, const int* in_sizes, int n_in,
                              void* d_out, int out_size) {
    const float* Xf = (const float*)d_in[0];   // batch_input (64,512,1024) f32
    const float* Wg = (const float*)d_in[1];   // W (1024,16) f32
    const float* b  = (const float*)d_in[2];   // b (16,) f32
    const int*   lb = (const int*)d_in[3];     // anchor_labels (64,512,8) i32
    float* out = (float*)d_out;

    cudaFuncSetAttribute(rpn_main_kernel,
                         cudaFuncAttributeMaxDynamicSharedMemorySize, SMEM_BYTES);
    rpn_main_kernel<<<NBLOCKS, THREADS, SMEM_BYTES>>>(Xf, Wg, b, lb, out);
}